// round 13
// baseline (speedup 1.0000x reference)
#include <cuda_runtime.h>

#define TTOK 4096
#define DM   1024
#define HID  4096
#define NE   8
#define YN   (TTOK * DM)

// ---- static scratch (no allocs allowed) ----
__device__ float g_buf1[2 * TTOK * HID];   // 128 MB: fc outputs / fused h (compact rows)
__device__ float g_buf2[2 * TTOK * HID];   // 128 MB: gate outputs
__device__ float g_rout[2 * TTOK * DM];    //  32 MB: routed proj outputs (compact rows)
__device__ float g_scores[TTOK * NE];
__device__ int   g_idx[NE * TTOK];         // padded per-expert token lists
__device__ int   g_apos[2 * TTOK];         // per token: encoded e*TTOK+slot, then compact pos
__device__ float g_aw[2 * TTOK];
__device__ int   g_cnt[NE];
__device__ int   g_off[NE];

__device__ __forceinline__ float to_tf32(float x) {
    unsigned u; asm("cvt.rna.tf32.f32 %0, %1;" : "=r"(u) : "f"(x));
    return __uint_as_float(u);
}
__device__ __forceinline__ void mma8(float* d, const float* a, const float* b) {
    const unsigned* A = reinterpret_cast<const unsigned*>(a);
    const unsigned* B = reinterpret_cast<const unsigned*>(b);
    asm volatile("mma.sync.aligned.m16n8k8.row.col.f32.tf32.tf32.f32 "
                 "{%0,%1,%2,%3}, {%4,%5,%6,%7}, {%8,%9}, {%0,%1,%2,%3};\n"
                 : "+f"(d[0]), "+f"(d[1]), "+f"(d[2]), "+f"(d[3])
                 : "r"(A[0]), "r"(A[1]), "r"(A[2]), "r"(A[3]), "r"(B[0]), "r"(B[1]));
}

__global__ void zero_k() {
    if (threadIdx.x < NE) g_cnt[threadIdx.x] = 0;
}

// ---- router: fp64 logits -> fp32 softmax + group-limited top-2 ----
__global__ void router_k(const float* __restrict__ x, const float* __restrict__ wr) {
    int t = blockIdx.x;
    const float* xr = x + (long long)t * DM;
    double acc[NE];
#pragma unroll
    for (int e = 0; e < NE; e++) acc[e] = 0.0;
    for (int d = threadIdx.x; d < DM; d += 256) {
        double xv = (double)xr[d];
#pragma unroll
        for (int e = 0; e < NE; e++) acc[e] += xv * (double)wr[e * DM + d];
    }
#pragma unroll
    for (int e = 0; e < NE; e++)
        for (int o = 16; o > 0; o >>= 1) acc[e] += __shfl_down_sync(0xffffffffu, acc[e], o);
    __shared__ double sred[NE][8];
    int lane = threadIdx.x & 31, w = threadIdx.x >> 5;
    if (lane == 0) {
#pragma unroll
        for (int e = 0; e < NE; e++) sred[e][w] = acc[e];
    }
    __syncthreads();
    if (threadIdx.x != 0) return;

    float lg[NE];
#pragma unroll
    for (int e = 0; e < NE; e++) {
        double s = 0.0;
#pragma unroll
        for (int k = 0; k < 8; k++) s += sred[e][k];
        lg[e] = (float)s;
    }
    float m = lg[0];
#pragma unroll
    for (int e = 1; e < NE; e++) m = fmaxf(m, lg[e]);
    float ex[NE], ssum = 0.f;
#pragma unroll
    for (int e = 0; e < NE; e++) { ex[e] = expf(lg[e] - m); ssum += ex[e]; }
    float sc[NE];
#pragma unroll
    for (int e = 0; e < NE; e++) { sc[e] = ex[e] / ssum; g_scores[t * NE + e] = sc[e]; }

    // group scores (4 groups of 2), pick top-2 groups; strict > keeps lowest index
    float gs[4];
#pragma unroll
    for (int gi = 0; gi < 4; gi++) gs[gi] = fmaxf(sc[2 * gi], sc[2 * gi + 1]);
    int g1 = 0;
#pragma unroll
    for (int gi = 1; gi < 4; gi++) if (gs[gi] > gs[g1]) g1 = gi;
    int g2 = -1; float bv = -1.f;
#pragma unroll
    for (int gi = 0; gi < 4; gi++) if (gi != g1 && gs[gi] > bv) { bv = gs[gi]; g2 = gi; }

    float msc[NE];
#pragma unroll
    for (int e = 0; e < NE; e++)
        msc[e] = (((e >> 1) == g1) || ((e >> 1) == g2)) ? sc[e] : -1.f;
    int i1 = 0;
#pragma unroll
    for (int e = 1; e < NE; e++) if (msc[e] > msc[i1]) i1 = e;
    int i2 = -1; float b2 = -2.f;
#pragma unroll
    for (int e = 0; e < NE; e++) if (e != i1 && msc[e] > b2) { b2 = msc[e]; i2 = e; }

    int s1 = atomicAdd(&g_cnt[i1], 1);
    g_idx[i1 * TTOK + s1] = t;
    g_apos[2 * t] = i1 * TTOK + s1;
    g_aw[2 * t] = sc[i1];
    int s2 = atomicAdd(&g_cnt[i2], 1);
    g_idx[i2 * TTOK + s2] = t;
    g_apos[2 * t + 1] = i2 * TTOK + s2;
    g_aw[2 * t + 1] = sc[i2];
}

__global__ void offsets_k() {
    if (threadIdx.x == 0) {
        int s = 0;
#pragma unroll
        for (int e = 0; e < NE; e++) { g_off[e] = s; s += g_cnt[e]; }
    }
}
__global__ void translate_k() {
    int t = blockIdx.x * blockDim.x + threadIdx.x;
    if (t >= 2 * TTOK) return;
    int code = g_apos[t];
    g_apos[t] = g_off[code >> 12] + (code & (TTOK - 1));
}

// ---- generic TF32 GEMM: C[M,N] = A[M,K] @ B[K,N] (B row-major) ----
__global__ __launch_bounds__(256, 2)
void gemm_k(const float* __restrict__ A, const float* __restrict__ B, float* __restrict__ C,
            int M, int N, int K, int lda, int ldc,
            const int* __restrict__ row_idx, const int* __restrict__ ecnt,
            const int* __restrict__ eoffs, long long strideB, int grouped)
{
    __shared__ float As[2][128][20];
    __shared__ float Bs[2][16][136];
    const int tid = threadIdx.x;
    const int n0 = blockIdx.x * 128;
    int valid, crow, arowbase;
    const float* Bp = B;
    if (grouped) {
        int e = blockIdx.y >> 5, mt = blockIdx.y & 31;
        int cnt = ecnt[e], base = mt * 128;
        if (base >= cnt) return;
        valid = cnt - base; if (valid > 128) valid = 128;
        crow = eoffs[e] + base;
        arowbase = row_idx ? (e * TTOK + base) : crow;
        Bp = B + (long long)e * strideB;
    } else {
        crow = blockIdx.y * 128;
        arowbase = crow;
        valid = M - crow; if (valid > 128) valid = 128;
    }

    const int ar0 = tid >> 2, ar1 = ar0 + 64, acol = (tid & 3) << 2;
    int r0 = arowbase + (ar0 < valid ? ar0 : valid - 1);
    int r1 = arowbase + (ar1 < valid ? ar1 : valid - 1);
    if (row_idx) { r0 = row_idx[r0]; r1 = row_idx[r1]; }
    const float* ap0 = A + (long long)r0 * lda + acol;
    const float* ap1 = A + (long long)r1 * lda + acol;
    const int br = tid >> 5, bcol = (tid & 31) << 2;
    const float* bp0 = Bp + (long long)br * N + n0 + bcol;
    const float* bp1 = bp0 + (long long)8 * N;

    float acc[2][8][4];
#pragma unroll
    for (int i = 0; i < 2; i++)
#pragma unroll
        for (int j = 0; j < 8; j++)
#pragma unroll
            for (int c = 0; c < 4; c++) acc[i][j][c] = 0.f;

    float4 ra0 = *(const float4*)ap0, ra1 = *(const float4*)ap1;
    float4 rb0 = *(const float4*)bp0, rb1 = *(const float4*)bp1;
    ap0 += 16; ap1 += 16; bp0 += (long long)16 * N; bp1 += (long long)16 * N;
    {
        float4 v;
        v.x=to_tf32(ra0.x); v.y=to_tf32(ra0.y); v.z=to_tf32(ra0.z); v.w=to_tf32(ra0.w);
        *(float4*)&As[0][ar0][acol] = v;
        v.x=to_tf32(ra1.x); v.y=to_tf32(ra1.y); v.z=to_tf32(ra1.z); v.w=to_tf32(ra1.w);
        *(float4*)&As[0][ar1][acol] = v;
        v.x=to_tf32(rb0.x); v.y=to_tf32(rb0.y); v.z=to_tf32(rb0.z); v.w=to_tf32(rb0.w);
        *(float4*)&Bs[0][br][bcol] = v;
        v.x=to_tf32(rb1.x); v.y=to_tf32(rb1.y); v.z=to_tf32(rb1.z); v.w=to_tf32(rb1.w);
        *(float4*)&Bs[0][br + 8][bcol] = v;
    }
    __syncthreads();

    const int lane = tid & 31, wid = tid >> 5;
    const int wm = (wid & 3) << 5, wn = (wid >> 2) << 6;
    const int g = lane >> 2, tg = lane & 3;
    const int nk = K >> 4;

    for (int kt = 0; kt < nk; kt++) {
        const int cur = kt & 1;
        const bool has = (kt + 1) < nk;
        if (has) {
            ra0 = *(const float4*)ap0; ra1 = *(const float4*)ap1;
            rb0 = *(const float4*)bp0; rb1 = *(const float4*)bp1;
            ap0 += 16; ap1 += 16; bp0 += (long long)16 * N; bp1 += (long long)16 * N;
        }
        const float (*Ac)[20]  = As[cur];
        const float (*Bc)[136] = Bs[cur];
#pragma unroll
        for (int s = 0; s < 2; s++) {
            const int ks = s << 3;
            float af[2][4], bf[8][2];
#pragma unroll
            for (int i = 0; i < 2; i++) {
                int mrow = wm + (i << 4) + g;
                af[i][0] = Ac[mrow][ks + tg];
                af[i][1] = Ac[mrow + 8][ks + tg];
                af[i][2] = Ac[mrow][ks + tg + 4];
                af[i][3] = Ac[mrow + 8][ks + tg + 4];
            }
#pragma unroll
            for (int j = 0; j < 8; j++) {
                int n = wn + (j << 3) + g;
                bf[j][0] = Bc[ks + tg][n];
                bf[j][1] = Bc[ks + tg + 4][n];
            }
#pragma unroll
            for (int i = 0; i < 2; i++)
#pragma unroll
                for (int j = 0; j < 8; j++) mma8(acc[i][j], af[i], bf[j]);
        }
        if (has) {
            const int nxt = cur ^ 1;
            float4 v;
            v.x=to_tf32(ra0.x); v.y=to_tf32(ra0.y); v.z=to_tf32(ra0.z); v.w=to_tf32(ra0.w);
            *(float4*)&As[nxt][ar0][acol] = v;
            v.x=to_tf32(ra1.x); v.y=to_tf32(ra1.y); v.z=to_tf32(ra1.z); v.w=to_tf32(ra1.w);
            *(float4*)&As[nxt][ar1][acol] = v;
            v.x=to_tf32(rb0.x); v.y=to_tf32(rb0.y); v.z=to_tf32(rb0.z); v.w=to_tf32(rb0.w);
            *(float4*)&Bs[nxt][br][bcol] = v;
            v.x=to_tf32(rb1.x); v.y=to_tf32(rb1.y); v.z=to_tf32(rb1.z); v.w=to_tf32(rb1.w);
            *(float4*)&Bs[nxt][br + 8][bcol] = v;
        }
        __syncthreads();
    }

#pragma unroll
    for (int i = 0; i < 2; i++) {
        int m0 = wm + (i << 4) + g, m1 = m0 + 8;
#pragma unroll
        for (int j = 0; j < 8; j++) {
            int c = n0 + wn + (j << 3) + (tg << 1);
            if (m0 < valid)
                *(float2*)&C[(long long)(crow + m0) * ldc + c] = make_float2(acc[i][j][0], acc[i][j][1]);
            if (m1 < valid)
                *(float2*)&C[(long long)(crow + m1) * ldc + c] = make_float2(acc[i][j][2], acc[i][j][3]);
        }
    }
}

// ---- h = fc * silu(gate) ----
__global__ void fuse_k(float4* __restrict__ h, const float4* __restrict__ gt, int n4) {
    int i = blockIdx.x * blockDim.x + threadIdx.x;
    if (i >= n4) return;
    float4 a = h[i], b = gt[i];
    a.x *= b.x / (1.f + __expf(-b.x));
    a.y *= b.y / (1.f + __expf(-b.y));
    a.z *= b.z / (1.f + __expf(-b.z));
    a.w *= b.w / (1.f + __expf(-b.w));
    h[i] = a;
}

// ---- y += w0*rout[p0] + w1*rout[p1] ----
__global__ void combine_k(float4* __restrict__ y, const float4* __restrict__ rout) {
    int v = blockIdx.x * blockDim.x + threadIdx.x;
    if (v >= YN / 4) return;
    int t = v >> 8, n = v & 255;
    int p0 = g_apos[2 * t], p1 = g_apos[2 * t + 1];
    float w0 = g_aw[2 * t], w1 = g_aw[2 * t + 1];
    float4 a = y[v];
    float4 q0 = rout[p0 * 256 + n], q1 = rout[p1 * 256 + n];
    a.x += w0 * q0.x + w1 * q1.x;
    a.y += w0 * q0.y + w1 * q1.y;
    a.z += w0 * q0.z + w1 * q1.z;
    a.w += w0 * q0.w + w1 * q1.w;
    y[v] = a;
}

// ---- lb_loss + counts tail ----
__global__ void tail_k(float* out, int out_size) {
    __shared__ float sh[NE][256];
    int tid = threadIdx.x;
    float ps[NE];
#pragma unroll
    for (int e = 0; e < NE; e++) ps[e] = 0.f;
    for (int t = tid; t < TTOK; t += 256)
#pragma unroll
        for (int e = 0; e < NE; e++) ps[e] += g_scores[t * NE + e];
#pragma unroll
    for (int e = 0; e < NE; e++) sh[e][tid] = ps[e];
    __syncthreads();
    __shared__ float pe[NE];
    if (tid < NE) {
        float s = 0.f;
        for (int k = 0; k < 256; k++) s += sh[tid][k];
        pe[tid] = s / (float)TTOK;
    }
    __syncthreads();
    if (tid == 0 && out_size > YN) {
        float lb = 0.f;
#pragma unroll
        for (int e = 0; e < NE; e++)
            lb += ((float)g_cnt[e] / (float)(TTOK * 2)) * pe[e];
        out[YN] = (float)NE * lb - 1.f;
    }
    if (tid < NE && out_size >= YN + 1 + NE)
        out[YN + 1 + tid] = (float)g_cnt[tid];
}

extern "C" void kernel_launch(void* const* d_in, const int* in_sizes, int n_in,
                              void* d_out, int out_size) {
    const float* x   = (const float*)d_in[0];
    const float* wr  = (const float*)d_in[1];
    const float* wfc = (const float*)d_in[2];
    const float* wgt = (const float*)d_in[3];
    const float* wpj = (const float*)d_in[4];
    const float* wsf = (const float*)d_in[5];
    const float* wsg = (const float*)d_in[6];
    const float* wsp = (const float*)d_in[7];
    float* y = (float*)d_out;

    void *p1, *p2, *pr, *pi, *pc, *po;
    cudaGetSymbolAddress(&p1, g_buf1);
    cudaGetSymbolAddress(&p2, g_buf2);
    cudaGetSymbolAddress(&pr, g_rout);
    cudaGetSymbolAddress(&pi, g_idx);
    cudaGetSymbolAddress(&pc, g_cnt);
    cudaGetSymbolAddress(&po, g_off);
    float* buf1 = (float*)p1;
    float* buf2 = (float*)p2;
    float* rout = (float*)pr;
    const int* idx = (const int*)pi;
    const int* cnt = (const int*)pc;
    const int* off = (const int*)po;

    zero_k<<<1, 32>>>();
    router_k<<<TTOK, 256>>>(x, wr);
    offsets_k<<<1, 32>>>();
    translate_k<<<(2 * TTOK + 255) / 256, 256>>>();

    // shared expert (proj writes y directly)
    gemm_k<<<dim3(HID / 128, TTOK / 128), 256>>>(x, wsf, buf1, TTOK, HID, DM, DM, HID,
                                                 nullptr, nullptr, nullptr, 0, 0);
    gemm_k<<<dim3(HID / 128, TTOK / 128), 256>>>(x, wsg, buf2, TTOK, HID, DM, DM, HID,
                                                 nullptr, nullptr, nullptr, 0, 0);
    fuse_k<<<(TTOK * HID / 4 + 255) / 256, 256>>>((float4*)buf1, (const float4*)buf2,
                                                  TTOK * HID / 4);
    gemm_k<<<dim3(DM / 128, TTOK / 128), 256>>>(buf1, wsp, y, TTOK, DM, HID, HID, DM,
                                                nullptr, nullptr, nullptr, 0, 0);

    // routed experts (grouped, compact rows; total assignments = 2*TTOK exactly)
    gemm_k<<<dim3(HID / 128, NE * 32), 256>>>(x, wfc, buf1, 0, HID, DM, DM, HID,
                                              idx, cnt, off, (long long)DM * HID, 1);
    gemm_k<<<dim3(HID / 128, NE * 32), 256>>>(x, wgt, buf2, 0, HID, DM, DM, HID,
                                              idx, cnt, off, (long long)DM * HID, 1);
    fuse_k<<<(2 * TTOK * HID / 4 + 255) / 256, 256>>>((float4*)buf1, (const float4*)buf2,
                                                      2 * TTOK * HID / 4);
    gemm_k<<<dim3(DM / 128, NE * 32), 256>>>(buf1, wpj, rout, 0, DM, HID, HID, DM,
                                             nullptr, cnt, off, (long long)HID * DM, 1);

    combine_k<<<(YN / 4 + 255) / 256, 256>>>((float4*)y, (const float4*)rout);
    tail_k<<<1, 256>>>(y, out_size);
}

// round 14
// speedup vs baseline: 1.0004x; 1.0004x over previous
#include <cuda_runtime.h>

#define TTOK 4096
#define DM   1024
#define HID  4096
#define NE   8
#define YN   (TTOK * DM)

// ---- static scratch (no allocs allowed) ----
__device__ float g_buf1[2 * TTOK * HID];   // 128 MB: fc outputs / fused h (compact rows)
__device__ float g_buf2[2 * TTOK * HID];   // 128 MB: gate outputs
__device__ float g_rout[2 * TTOK * DM];    //  32 MB: routed proj outputs (compact rows)
__device__ float g_scores[TTOK * NE];
__device__ int   g_idx[NE * TTOK];         // padded per-expert token lists
__device__ int   g_apos[2 * TTOK];         // per token: encoded e*TTOK+slot, then compact pos
__device__ float g_aw[2 * TTOK];
__device__ int   g_cnt[NE];
__device__ int   g_off[NE];

__device__ __forceinline__ float to_tf32(float x) {
    unsigned u; asm("cvt.rna.tf32.f32 %0, %1;" : "=r"(u) : "f"(x));
    return __uint_as_float(u);
}
__device__ __forceinline__ void mma8(float* d, const float* a, const float* b) {
    const unsigned* A = reinterpret_cast<const unsigned*>(a);
    const unsigned* B = reinterpret_cast<const unsigned*>(b);
    asm volatile("mma.sync.aligned.m16n8k8.row.col.f32.tf32.tf32.f32 "
                 "{%0,%1,%2,%3}, {%4,%5,%6,%7}, {%8,%9}, {%0,%1,%2,%3};\n"
                 : "+f"(d[0]), "+f"(d[1]), "+f"(d[2]), "+f"(d[3])
                 : "r"(A[0]), "r"(A[1]), "r"(A[2]), "r"(A[3]), "r"(B[0]), "r"(B[1]));
}

__global__ void zero_k() {
    if (threadIdx.x < NE) g_cnt[threadIdx.x] = 0;
}

// ---- router: fp64 logits -> fp32 softmax + group-limited top-2 ----
__global__ void router_k(const float* __restrict__ x, const float* __restrict__ wr) {
    int t = blockIdx.x;
    const float* xr = x + (long long)t * DM;
    double acc[NE];
#pragma unroll
    for (int e = 0; e < NE; e++) acc[e] = 0.0;
    for (int d = threadIdx.x; d < DM; d += 256) {
        double xv = (double)xr[d];
#pragma unroll
        for (int e = 0; e < NE; e++) acc[e] += xv * (double)wr[e * DM + d];
    }
#pragma unroll
    for (int e = 0; e < NE; e++)
        for (int o = 16; o > 0; o >>= 1) acc[e] += __shfl_down_sync(0xffffffffu, acc[e], o);
    __shared__ double sred[NE][8];
    int lane = threadIdx.x & 31, w = threadIdx.x >> 5;
    if (lane == 0) {
#pragma unroll
        for (int e = 0; e < NE; e++) sred[e][w] = acc[e];
    }
    __syncthreads();
    if (threadIdx.x != 0) return;

    float lg[NE];
#pragma unroll
    for (int e = 0; e < NE; e++) {
        double s = 0.0;
#pragma unroll
        for (int k = 0; k < 8; k++) s += sred[e][k];
        lg[e] = (float)s;
    }
    float m = lg[0];
#pragma unroll
    for (int e = 1; e < NE; e++) m = fmaxf(m, lg[e]);
    float ex[NE], ssum = 0.f;
#pragma unroll
    for (int e = 0; e < NE; e++) { ex[e] = expf(lg[e] - m); ssum += ex[e]; }
    float sc[NE];
#pragma unroll
    for (int e = 0; e < NE; e++) { sc[e] = ex[e] / ssum; g_scores[t * NE + e] = sc[e]; }

    // group scores (4 groups of 2), pick top-2 groups; strict > keeps lowest index
    float gs[4];
#pragma unroll
    for (int gi = 0; gi < 4; gi++) gs[gi] = fmaxf(sc[2 * gi], sc[2 * gi + 1]);
    int g1 = 0;
#pragma unroll
    for (int gi = 1; gi < 4; gi++) if (gs[gi] > gs[g1]) g1 = gi;
    int g2 = -1; float bv = -1.f;
#pragma unroll
    for (int gi = 0; gi < 4; gi++) if (gi != g1 && gs[gi] > bv) { bv = gs[gi]; g2 = gi; }

    float msc[NE];
#pragma unroll
    for (int e = 0; e < NE; e++)
        msc[e] = (((e >> 1) == g1) || ((e >> 1) == g2)) ? sc[e] : -1.f;
    int i1 = 0;
#pragma unroll
    for (int e = 1; e < NE; e++) if (msc[e] > msc[i1]) i1 = e;
    int i2 = -1; float b2 = -2.f;
#pragma unroll
    for (int e = 0; e < NE; e++) if (e != i1 && msc[e] > b2) { b2 = msc[e]; i2 = e; }

    int s1 = atomicAdd(&g_cnt[i1], 1);
    g_idx[i1 * TTOK + s1] = t;
    g_apos[2 * t] = i1 * TTOK + s1;
    g_aw[2 * t] = sc[i1];
    int s2 = atomicAdd(&g_cnt[i2], 1);
    g_idx[i2 * TTOK + s2] = t;
    g_apos[2 * t + 1] = i2 * TTOK + s2;
    g_aw[2 * t + 1] = sc[i2];
}

__global__ void offsets_k() {
    if (threadIdx.x == 0) {
        int s = 0;
#pragma unroll
        for (int e = 0; e < NE; e++) { g_off[e] = s; s += g_cnt[e]; }
    }
}
__global__ void translate_k() {
    int t = blockIdx.x * blockDim.x + threadIdx.x;
    if (t >= 2 * TTOK) return;
    int code = g_apos[t];
    g_apos[t] = g_off[code >> 12] + (code & (TTOK - 1));
}

// ---- generic TF32 GEMM: C[M,N] = A[M,K] @ B[K,N] (B row-major) ----
__global__ __launch_bounds__(256, 2)
void gemm_k(const float* __restrict__ A, const float* __restrict__ B, float* __restrict__ C,
            int M, int N, int K, int lda, int ldc,
            const int* __restrict__ row_idx, const int* __restrict__ ecnt,
            const int* __restrict__ eoffs, long long strideB, int grouped)
{
    __shared__ float As[2][128][20];
    __shared__ float Bs[2][16][136];
    const int tid = threadIdx.x;
    const int n0 = blockIdx.x * 128;
    int valid, crow, arowbase;
    const float* Bp = B;
    if (grouped) {
        int e = blockIdx.y >> 5, mt = blockIdx.y & 31;
        int cnt = ecnt[e], base = mt * 128;
        if (base >= cnt) return;
        valid = cnt - base; if (valid > 128) valid = 128;
        crow = eoffs[e] + base;
        arowbase = row_idx ? (e * TTOK + base) : crow;
        Bp = B + (long long)e * strideB;
    } else {
        crow = blockIdx.y * 128;
        arowbase = crow;
        valid = M - crow; if (valid > 128) valid = 128;
    }

    const int ar0 = tid >> 2, ar1 = ar0 + 64, acol = (tid & 3) << 2;
    int r0 = arowbase + (ar0 < valid ? ar0 : valid - 1);
    int r1 = arowbase + (ar1 < valid ? ar1 : valid - 1);
    if (row_idx) { r0 = row_idx[r0]; r1 = row_idx[r1]; }
    const float* ap0 = A + (long long)r0 * lda + acol;
    const float* ap1 = A + (long long)r1 * lda + acol;
    const int br = tid >> 5, bcol = (tid & 31) << 2;
    const float* bp0 = Bp + (long long)br * N + n0 + bcol;
    const float* bp1 = bp0 + (long long)8 * N;

    float acc[2][8][4];
#pragma unroll
    for (int i = 0; i < 2; i++)
#pragma unroll
        for (int j = 0; j < 8; j++)
#pragma unroll
            for (int c = 0; c < 4; c++) acc[i][j][c] = 0.f;

    float4 ra0 = *(const float4*)ap0, ra1 = *(const float4*)ap1;
    float4 rb0 = *(const float4*)bp0, rb1 = *(const float4*)bp1;
    ap0 += 16; ap1 += 16; bp0 += (long long)16 * N; bp1 += (long long)16 * N;
    {
        float4 v;
        v.x=to_tf32(ra0.x); v.y=to_tf32(ra0.y); v.z=to_tf32(ra0.z); v.w=to_tf32(ra0.w);
        *(float4*)&As[0][ar0][acol] = v;
        v.x=to_tf32(ra1.x); v.y=to_tf32(ra1.y); v.z=to_tf32(ra1.z); v.w=to_tf32(ra1.w);
        *(float4*)&As[0][ar1][acol] = v;
        v.x=to_tf32(rb0.x); v.y=to_tf32(rb0.y); v.z=to_tf32(rb0.z); v.w=to_tf32(rb0.w);
        *(float4*)&Bs[0][br][bcol] = v;
        v.x=to_tf32(rb1.x); v.y=to_tf32(rb1.y); v.z=to_tf32(rb1.z); v.w=to_tf32(rb1.w);
        *(float4*)&Bs[0][br + 8][bcol] = v;
    }
    __syncthreads();

    const int lane = tid & 31, wid = tid >> 5;
    const int wm = (wid & 3) << 5, wn = (wid >> 2) << 6;
    const int g = lane >> 2, tg = lane & 3;
    const int nk = K >> 4;

    for (int kt = 0; kt < nk; kt++) {
        const int cur = kt & 1;
        const bool has = (kt + 1) < nk;
        if (has) {
            ra0 = *(const float4*)ap0; ra1 = *(const float4*)ap1;
            rb0 = *(const float4*)bp0; rb1 = *(const float4*)bp1;
            ap0 += 16; ap1 += 16; bp0 += (long long)16 * N; bp1 += (long long)16 * N;
        }
        const float (*Ac)[20]  = As[cur];
        const float (*Bc)[136] = Bs[cur];
#pragma unroll
        for (int s = 0; s < 2; s++) {
            const int ks = s << 3;
            float af[2][4], bf[8][2];
#pragma unroll
            for (int i = 0; i < 2; i++) {
                int mrow = wm + (i << 4) + g;
                af[i][0] = Ac[mrow][ks + tg];
                af[i][1] = Ac[mrow + 8][ks + tg];
                af[i][2] = Ac[mrow][ks + tg + 4];
                af[i][3] = Ac[mrow + 8][ks + tg + 4];
            }
#pragma unroll
            for (int j = 0; j < 8; j++) {
                int n = wn + (j << 3) + g;
                bf[j][0] = Bc[ks + tg][n];
                bf[j][1] = Bc[ks + tg + 4][n];
            }
#pragma unroll
            for (int i = 0; i < 2; i++)
#pragma unroll
                for (int j = 0; j < 8; j++) mma8(acc[i][j], af[i], bf[j]);
        }
        if (has) {
            const int nxt = cur ^ 1;
            float4 v;
            v.x=to_tf32(ra0.x); v.y=to_tf32(ra0.y); v.z=to_tf32(ra0.z); v.w=to_tf32(ra0.w);
            *(float4*)&As[nxt][ar0][acol] = v;
            v.x=to_tf32(ra1.x); v.y=to_tf32(ra1.y); v.z=to_tf32(ra1.z); v.w=to_tf32(ra1.w);
            *(float4*)&As[nxt][ar1][acol] = v;
            v.x=to_tf32(rb0.x); v.y=to_tf32(rb0.y); v.z=to_tf32(rb0.z); v.w=to_tf32(rb0.w);
            *(float4*)&Bs[nxt][br][bcol] = v;
            v.x=to_tf32(rb1.x); v.y=to_tf32(rb1.y); v.z=to_tf32(rb1.z); v.w=to_tf32(rb1.w);
            *(float4*)&Bs[nxt][br + 8][bcol] = v;
        }
        __syncthreads();
    }

#pragma unroll
    for (int i = 0; i < 2; i++) {
        int m0 = wm + (i << 4) + g, m1 = m0 + 8;
#pragma unroll
        for (int j = 0; j < 8; j++) {
            int c = n0 + wn + (j << 3) + (tg << 1);
            if (m0 < valid)
                *(float2*)&C[(long long)(crow + m0) * ldc + c] = make_float2(acc[i][j][0], acc[i][j][1]);
            if (m1 < valid)
                *(float2*)&C[(long long)(crow + m1) * ldc + c] = make_float2(acc[i][j][2], acc[i][j][3]);
        }
    }
}

// ---- h = fc * silu(gate) ----
__global__ void fuse_k(float4* __restrict__ h, const float4* __restrict__ gt, int n4) {
    int i = blockIdx.x * blockDim.x + threadIdx.x;
    if (i >= n4) return;
    float4 a = h[i], b = gt[i];
    a.x *= b.x / (1.f + __expf(-b.x));
    a.y *= b.y / (1.f + __expf(-b.y));
    a.z *= b.z / (1.f + __expf(-b.z));
    a.w *= b.w / (1.f + __expf(-b.w));
    h[i] = a;
}

// ---- y += w0*rout[p0] + w1*rout[p1] ----
__global__ void combine_k(float4* __restrict__ y, const float4* __restrict__ rout) {
    int v = blockIdx.x * blockDim.x + threadIdx.x;
    if (v >= YN / 4) return;
    int t = v >> 8, n = v & 255;
    int p0 = g_apos[2 * t], p1 = g_apos[2 * t + 1];
    float w0 = g_aw[2 * t], w1 = g_aw[2 * t + 1];
    float4 a = y[v];
    float4 q0 = rout[p0 * 256 + n], q1 = rout[p1 * 256 + n];
    a.x += w0 * q0.x + w1 * q1.x;
    a.y += w0 * q0.y + w1 * q1.y;
    a.z += w0 * q0.z + w1 * q1.z;
    a.w += w0 * q0.w + w1 * q1.w;
    y[v] = a;
}

// ---- lb_loss + counts tail ----
__global__ void tail_k(float* out, int out_size) {
    __shared__ float sh[NE][256];
    int tid = threadIdx.x;
    float ps[NE];
#pragma unroll
    for (int e = 0; e < NE; e++) ps[e] = 0.f;
    for (int t = tid; t < TTOK; t += 256)
#pragma unroll
        for (int e = 0; e < NE; e++) ps[e] += g_scores[t * NE + e];
#pragma unroll
    for (int e = 0; e < NE; e++) sh[e][tid] = ps[e];
    __syncthreads();
    __shared__ float pe[NE];
    if (tid < NE) {
        float s = 0.f;
        for (int k = 0; k < 256; k++) s += sh[tid][k];
        pe[tid] = s / (float)TTOK;
    }
    __syncthreads();
    if (tid == 0 && out_size > YN) {
        float lb = 0.f;
#pragma unroll
        for (int e = 0; e < NE; e++)
            lb += ((float)g_cnt[e] / (float)(TTOK * 2)) * pe[e];
        out[YN] = (float)NE * lb - 1.f;
    }
    if (tid < NE && out_size >= YN + 1 + NE)
        out[YN + 1 + tid] = (float)g_cnt[tid];
}

extern "C" void kernel_launch(void* const* d_in, const int* in_sizes, int n_in,
                              void* d_out, int out_size) {
    const float* x   = (const float*)d_in[0];
    const float* wr  = (const float*)d_in[1];
    const float* wfc = (const float*)d_in[2];
    const float* wgt = (const float*)d_in[3];
    const float* wpj = (const float*)d_in[4];
    const float* wsf = (const float*)d_in[5];
    const float* wsg = (const float*)d_in[6];
    const float* wsp = (const float*)d_in[7];
    float* y = (float*)d_out;

    void *p1, *p2, *pr, *pi, *pc, *po;
    cudaGetSymbolAddress(&p1, g_buf1);
    cudaGetSymbolAddress(&p2, g_buf2);
    cudaGetSymbolAddress(&pr, g_rout);
    cudaGetSymbolAddress(&pi, g_idx);
    cudaGetSymbolAddress(&pc, g_cnt);
    cudaGetSymbolAddress(&po, g_off);
    float* buf1 = (float*)p1;
    float* buf2 = (float*)p2;
    float* rout = (float*)pr;
    const int* idx = (const int*)pi;
    const int* cnt = (const int*)pc;
    const int* off = (const int*)po;

    zero_k<<<1, 32>>>();
    router_k<<<TTOK, 256>>>(x, wr);
    offsets_k<<<1, 32>>>();
    translate_k<<<(2 * TTOK + 255) / 256, 256>>>();

    // shared expert (proj writes y directly)
    gemm_k<<<dim3(HID / 128, TTOK / 128), 256>>>(x, wsf, buf1, TTOK, HID, DM, DM, HID,
                                                 nullptr, nullptr, nullptr, 0, 0);
    gemm_k<<<dim3(HID / 128, TTOK / 128), 256>>>(x, wsg, buf2, TTOK, HID, DM, DM, HID,
                                                 nullptr, nullptr, nullptr, 0, 0);
    fuse_k<<<(TTOK * HID / 4 + 255) / 256, 256>>>((float4*)buf1, (const float4*)buf2,
                                                  TTOK * HID / 4);
    gemm_k<<<dim3(DM / 128, TTOK / 128), 256>>>(buf1, wsp, y, TTOK, DM, HID, HID, DM,
                                                nullptr, nullptr, nullptr, 0, 0);

    // routed experts (grouped, compact rows; total assignments = 2*TTOK exactly)
    gemm_k<<<dim3(HID / 128, NE * 32), 256>>>(x, wfc, buf1, 0, HID, DM, DM, HID,
                                              idx, cnt, off, (long long)DM * HID, 1);
    gemm_k<<<dim3(HID / 128, NE * 32), 256>>>(x, wgt, buf2, 0, HID, DM, DM, HID,
                                              idx, cnt, off, (long long)DM * HID, 1);
    fuse_k<<<(2 * TTOK * HID / 4 + 255) / 256, 256>>>((float4*)buf1, (const float4*)buf2,
                                                      2 * TTOK * HID / 4);
    gemm_k<<<dim3(DM / 128, NE * 32), 256>>>(buf1, wpj, rout, 0, DM, HID, HID, DM,
                                             nullptr, cnt, off, (long long)HID * DM, 1);

    combine_k<<<(YN / 4 + 255) / 256, 256>>>((float4*)y, (const float4*)rout);
    tail_k<<<1, 256>>>(y, out_size);
}

// round 16
// speedup vs baseline: 1.0143x; 1.0139x over previous
#include <cuda_runtime.h>
#include <cuda_bf16.h>
#include <cstdint>

#define TTOK 4096
#define DM   1024
#define HID  4096
#define NE   8
#define YN   (TTOK * DM)

// GEMM tiling
#define BM 128
#define BN 256
#define BK 16
#define NSTAGE 3
#define A_LD 20                 // floats per A smem row (16 + 4 pad)
#define B_LD 264                // floats per B smem row (256 + 8 pad)
#define ASZ_B (128 * A_LD * 4)  // 10240 bytes
#define BSZ_B (16 * B_LD * 4)   // 16896 bytes
#define STG_B (ASZ_B + BSZ_B)   // 27136 bytes
#define GEMM_SMEM (NSTAGE * STG_B)  // 81408 bytes

// ---- static scratch ----
__device__ float g_buf1[2 * TTOK * HID];
__device__ float g_buf2[2 * TTOK * HID];
__device__ float g_rout[2 * TTOK * DM];
__device__ float g_scores[TTOK * NE];
__device__ int   g_idx[NE * TTOK];
__device__ int   g_apos[2 * TTOK];
__device__ float g_aw[2 * TTOK];
__device__ int   g_cnt[NE];
__device__ int   g_off[NE];

// ---- helpers ----
__device__ __forceinline__ uint32_t smem_u32(const void* p) {
    uint32_t a;
    asm("{ .reg .u64 t; cvta.to.shared.u64 t, %1; cvt.u32.u64 %0, t; }" : "=r"(a) : "l"(p));
    return a;
}
__device__ __forceinline__ float to_tf32(float x) {
    unsigned u; asm("cvt.rna.tf32.f32 %0, %1;" : "=r"(u) : "f"(x));
    return __uint_as_float(u);
}
__device__ __forceinline__ void mma8(float* d, const float* a, const float* b) {
    const unsigned* A = reinterpret_cast<const unsigned*>(a);
    const unsigned* B = reinterpret_cast<const unsigned*>(b);
    asm volatile("mma.sync.aligned.m16n8k8.row.col.f32.tf32.tf32.f32 "
                 "{%0,%1,%2,%3}, {%4,%5,%6,%7}, {%8,%9}, {%0,%1,%2,%3};\n"
                 : "+f"(d[0]), "+f"(d[1]), "+f"(d[2]), "+f"(d[3])
                 : "r"(A[0]), "r"(A[1]), "r"(A[2]), "r"(A[3]), "r"(B[0]), "r"(B[1]));
}
__device__ __forceinline__ void cpasync16(uint32_t dst, const float* src) {
    asm volatile("cp.async.cg.shared.global [%0], [%1], 16;" :: "r"(dst), "l"(src));
}
#define CP_COMMIT() asm volatile("cp.async.commit_group;" ::: "memory")
#define CP_WAIT1()  asm volatile("cp.async.wait_group 1;" ::: "memory")

// ================= TF32 GEMM, cp.async 3-stage, warp tile 64x64 =================
// C[M,N] = A[M,K] @ B[K,N] (row-major). grouped: blockIdx.y = e*32+mt, rows from
// compact layout (eoffs/ecnt); row_idx gathers A rows.
__global__ __launch_bounds__(256)
void gemm_tc(const float* __restrict__ A, const float* __restrict__ B, float* __restrict__ C,
             int Mtot, int N, int K, int lda, int ldc,
             const int* __restrict__ row_idx, const int* __restrict__ ecnt,
             const int* __restrict__ eoffs, long long strideB, int grouped)
{
    extern __shared__ float smem[];
    const int tid = threadIdx.x;
    const int n0 = blockIdx.x * BN;

    int valid, crow, arowbase;
    const float* Bp = B;
    if (grouped) {
        int e = blockIdx.y >> 5, mt = blockIdx.y & 31;
        int cnt = ecnt[e], base = mt * BM;
        if (base >= cnt) return;
        valid = cnt - base; if (valid > BM) valid = BM;
        crow = eoffs[e] + base;
        arowbase = row_idx ? (e * TTOK + base) : crow;
        Bp = B + (long long)e * strideB;
    } else {
        crow = blockIdx.y * BM;
        arowbase = crow;
        valid = Mtot - crow; if (valid > BM) valid = BM;
    }

    // ---- fill assignments ----
    const int fr0 = tid >> 2;        // A rows 0..63
    const int fr1 = fr0 + 64;        // A rows 64..127
    const int fq  = tid & 3;         // A k-quad
    int gr0 = arowbase + (fr0 < valid ? fr0 : valid - 1);
    int gr1 = arowbase + (fr1 < valid ? fr1 : valid - 1);
    if (row_idx) { gr0 = row_idx[gr0]; gr1 = row_idx[gr1]; }
    const float* asrc0 = A + (long long)gr0 * lda + fq * 4;
    const float* asrc1 = A + (long long)gr1 * lda + fq * 4;
    const int fkb = tid >> 6;        // B k row base 0..3 (+4i)
    const int fnq = tid & 63;        // B n-quad
    const float* bsrc = Bp + n0 + fnq * 4;

    const uint32_t sb = smem_u32(smem);
    const int nk = K >> 4;

    auto issue = [&](int s, int k0) {
        if (k0 < K) {
            uint32_t st = sb + s * STG_B;
            cpasync16(st + fr0 * (A_LD * 4) + fq * 16, asrc0 + k0);
            cpasync16(st + fr1 * (A_LD * 4) + fq * 16, asrc1 + k0);
            uint32_t bb = st + ASZ_B;
#pragma unroll
            for (int i = 0; i < 4; i++) {
                int k = fkb + 4 * i;
                cpasync16(bb + k * (B_LD * 4) + fnq * 16, bsrc + (long long)(k0 + k) * N);
            }
        }
        CP_COMMIT();
    };

    issue(0, 0);
    issue(1, BK);

    // ---- compute mapping: 8 warps as 2(m) x 4(n), warp tile 64x64 ----
    const int wid = tid >> 5, lane = tid & 31;
    const int wm = (wid & 1) << 6;
    const int wn = (wid >> 1) << 6;
    const int g = lane >> 2, tg = lane & 3;

    float acc[4][8][4];
#pragma unroll
    for (int i = 0; i < 4; i++)
#pragma unroll
        for (int j = 0; j < 8; j++)
#pragma unroll
            for (int c = 0; c < 4; c++) acc[i][j][c] = 0.f;

    for (int it = 0; it < nk; ++it) {
        CP_WAIT1();
        __syncthreads();
        issue((it + 2) % NSTAGE, (it + 2) * BK);

        const float* Sa = smem + (it % NSTAGE) * (STG_B / 4);
        const float* Sb = Sa + (ASZ_B / 4);
#pragma unroll
        for (int s = 0; s < 2; s++) {
            const int ks = s << 3;
            float af[4][4], bf[8][2];
#pragma unroll
            for (int j = 0; j < 8; j++) {
                int n = wn + (j << 3) + g;
                bf[j][0] = to_tf32(Sb[(ks + tg) * B_LD + n]);
                bf[j][1] = to_tf32(Sb[(ks + tg + 4) * B_LD + n]);
            }
#pragma unroll
            for (int i = 0; i < 4; i++) {
                int m = wm + (i << 4) + g;
                af[i][0] = to_tf32(Sa[m * A_LD + ks + tg]);
                af[i][1] = to_tf32(Sa[(m + 8) * A_LD + ks + tg]);
                af[i][2] = to_tf32(Sa[m * A_LD + ks + tg + 4]);
                af[i][3] = to_tf32(Sa[(m + 8) * A_LD + ks + tg + 4]);
            }
#pragma unroll
            for (int i = 0; i < 4; i++)
#pragma unroll
                for (int j = 0; j < 8; j++) mma8(acc[i][j], af[i], bf[j]);
        }
    }

    // ---- epilogue: direct fp32 stores ----
#pragma unroll
    for (int i = 0; i < 4; i++) {
        int m0 = wm + (i << 4) + g, m1 = m0 + 8;
#pragma unroll
        for (int j = 0; j < 8; j++) {
            int c = n0 + wn + (j << 3) + (tg << 1);
            if (m0 < valid)
                *(float2*)&C[(long long)(crow + m0) * ldc + c] = make_float2(acc[i][j][0], acc[i][j][1]);
            if (m1 < valid)
                *(float2*)&C[(long long)(crow + m1) * ldc + c] = make_float2(acc[i][j][2], acc[i][j][3]);
        }
    }
}

// ================= router / small kernels (proven in R14) =================
__global__ void zero_k() {
    if (threadIdx.x < NE) g_cnt[threadIdx.x] = 0;
}

__global__ void router_k(const float* __restrict__ x, const float* __restrict__ wr) {
    int t = blockIdx.x;
    const float* xr = x + (long long)t * DM;
    double acc[NE];
#pragma unroll
    for (int e = 0; e < NE; e++) acc[e] = 0.0;
    for (int d = threadIdx.x; d < DM; d += 256) {
        double xv = (double)xr[d];
#pragma unroll
        for (int e = 0; e < NE; e++) acc[e] += xv * (double)wr[e * DM + d];
    }
#pragma unroll
    for (int e = 0; e < NE; e++)
        for (int o = 16; o > 0; o >>= 1) acc[e] += __shfl_down_sync(0xffffffffu, acc[e], o);
    __shared__ double sred[NE][8];
    int lane = threadIdx.x & 31, w = threadIdx.x >> 5;
    if (lane == 0) {
#pragma unroll
        for (int e = 0; e < NE; e++) sred[e][w] = acc[e];
    }
    __syncthreads();
    if (threadIdx.x != 0) return;

    float lg[NE];
#pragma unroll
    for (int e = 0; e < NE; e++) {
        double s = 0.0;
#pragma unroll
        for (int k = 0; k < 8; k++) s += sred[e][k];
        lg[e] = (float)s;
    }
    float m = lg[0];
#pragma unroll
    for (int e = 1; e < NE; e++) m = fmaxf(m, lg[e]);
    float ex[NE], ssum = 0.f;
#pragma unroll
    for (int e = 0; e < NE; e++) { ex[e] = expf(lg[e] - m); ssum += ex[e]; }
    float sc[NE];
#pragma unroll
    for (int e = 0; e < NE; e++) { sc[e] = ex[e] / ssum; g_scores[t * NE + e] = sc[e]; }

    float gs[4];
#pragma unroll
    for (int gi = 0; gi < 4; gi++) gs[gi] = fmaxf(sc[2 * gi], sc[2 * gi + 1]);
    int g1 = 0;
#pragma unroll
    for (int gi = 1; gi < 4; gi++) if (gs[gi] > gs[g1]) g1 = gi;
    int g2 = -1; float bv = -1.f;
#pragma unroll
    for (int gi = 0; gi < 4; gi++) if (gi != g1 && gs[gi] > bv) { bv = gs[gi]; g2 = gi; }

    float msc[NE];
#pragma unroll
    for (int e = 0; e < NE; e++)
        msc[e] = (((e >> 1) == g1) || ((e >> 1) == g2)) ? sc[e] : -1.f;
    int i1 = 0;
#pragma unroll
    for (int e = 1; e < NE; e++) if (msc[e] > msc[i1]) i1 = e;
    int i2 = -1; float b2 = -2.f;
#pragma unroll
    for (int e = 0; e < NE; e++) if (e != i1 && msc[e] > b2) { b2 = msc[e]; i2 = e; }

    int s1 = atomicAdd(&g_cnt[i1], 1);
    g_idx[i1 * TTOK + s1] = t;
    g_apos[2 * t] = i1 * TTOK + s1;
    g_aw[2 * t] = sc[i1];
    int s2 = atomicAdd(&g_cnt[i2], 1);
    g_idx[i2 * TTOK + s2] = t;
    g_apos[2 * t + 1] = i2 * TTOK + s2;
    g_aw[2 * t + 1] = sc[i2];
}

__global__ void offsets_k() {
    if (threadIdx.x == 0) {
        int s = 0;
#pragma unroll
        for (int e = 0; e < NE; e++) { g_off[e] = s; s += g_cnt[e]; }
    }
}
__global__ void translate_k() {
    int t = blockIdx.x * blockDim.x + threadIdx.x;
    if (t >= 2 * TTOK) return;
    int code = g_apos[t];
    g_apos[t] = g_off[code >> 12] + (code & (TTOK - 1));
}

__global__ void fuse_k(float4* __restrict__ h, const float4* __restrict__ gt, int n4) {
    int i = blockIdx.x * blockDim.x + threadIdx.x;
    if (i >= n4) return;
    float4 a = h[i], b = gt[i];
    a.x *= b.x / (1.f + __expf(-b.x));
    a.y *= b.y / (1.f + __expf(-b.y));
    a.z *= b.z / (1.f + __expf(-b.z));
    a.w *= b.w / (1.f + __expf(-b.w));
    h[i] = a;
}

__global__ void combine_k(float4* __restrict__ y, const float4* __restrict__ rout) {
    int v = blockIdx.x * blockDim.x + threadIdx.x;
    if (v >= YN / 4) return;
    int t = v >> 8, n = v & 255;
    int p0 = g_apos[2 * t], p1 = g_apos[2 * t + 1];
    float w0 = g_aw[2 * t], w1 = g_aw[2 * t + 1];
    float4 a = y[v];
    float4 q0 = rout[p0 * 256 + n], q1 = rout[p1 * 256 + n];
    a.x += w0 * q0.x + w1 * q1.x;
    a.y += w0 * q0.y + w1 * q1.y;
    a.z += w0 * q0.z + w1 * q1.z;
    a.w += w0 * q0.w + w1 * q1.w;
    y[v] = a;
}

__global__ void tail_k(float* out, int out_size) {
    __shared__ float sh[NE][256];
    int tid = threadIdx.x;
    float ps[NE];
#pragma unroll
    for (int e = 0; e < NE; e++) ps[e] = 0.f;
    for (int t = tid; t < TTOK; t += 256)
#pragma unroll
        for (int e = 0; e < NE; e++) ps[e] += g_scores[t * NE + e];
#pragma unroll
    for (int e = 0; e < NE; e++) sh[e][tid] = ps[e];
    __syncthreads();
    __shared__ float pe[NE];
    if (tid < NE) {
        float s = 0.f;
        for (int k = 0; k < 256; k++) s += sh[tid][k];
        pe[tid] = s / (float)TTOK;
    }
    __syncthreads();
    if (tid == 0 && out_size > YN) {
        float lb = 0.f;
#pragma unroll
        for (int e = 0; e < NE; e++)
            lb += ((float)g_cnt[e] / (float)(TTOK * 2)) * pe[e];
        out[YN] = (float)NE * lb - 1.f;
    }
    if (tid < NE && out_size >= YN + 1 + NE)
        out[YN + 1 + tid] = (float)g_cnt[tid];
}

// ================= launch =================
extern "C" void kernel_launch(void* const* d_in, const int* in_sizes, int n_in,
                              void* d_out, int out_size) {
    const float* x   = (const float*)d_in[0];
    const float* wr  = (const float*)d_in[1];
    const float* wfc = (const float*)d_in[2];
    const float* wgt = (const float*)d_in[3];
    const float* wpj = (const float*)d_in[4];
    const float* wsf = (const float*)d_in[5];
    const float* wsg = (const float*)d_in[6];
    const float* wsp = (const float*)d_in[7];
    float* y = (float*)d_out;

    cudaFuncSetAttribute(gemm_tc, cudaFuncAttributeMaxDynamicSharedMemorySize, GEMM_SMEM);

    void *p1, *p2, *pr, *pi, *pc, *po;
    cudaGetSymbolAddress(&p1, g_buf1);
    cudaGetSymbolAddress(&p2, g_buf2);
    cudaGetSymbolAddress(&pr, g_rout);
    cudaGetSymbolAddress(&pi, g_idx);
    cudaGetSymbolAddress(&pc, g_cnt);
    cudaGetSymbolAddress(&po, g_off);
    float* buf1 = (float*)p1;
    float* buf2 = (float*)p2;
    float* rout = (float*)pr;
    const int* idx = (const int*)pi;
    const int* cnt = (const int*)pc;
    const int* off = (const int*)po;

    zero_k<<<1, 32>>>();
    router_k<<<TTOK, 256>>>(x, wr);
    offsets_k<<<1, 32>>>();
    translate_k<<<(2 * TTOK + 255) / 256, 256>>>();

    // shared expert (proj writes y directly)
    gemm_tc<<<dim3(HID / BN, TTOK / BM), 256, GEMM_SMEM>>>(
        x, wsf, buf1, TTOK, HID, DM, DM, HID, nullptr, nullptr, nullptr, 0, 0);
    gemm_tc<<<dim3(HID / BN, TTOK / BM), 256, GEMM_SMEM>>>(
        x, wsg, buf2, TTOK, HID, DM, DM, HID, nullptr, nullptr, nullptr, 0, 0);
    fuse_k<<<(TTOK * HID / 4 + 255) / 256, 256>>>((float4*)buf1, (const float4*)buf2,
                                                  TTOK * HID / 4);
    gemm_tc<<<dim3(DM / BN, TTOK / BM), 256, GEMM_SMEM>>>(
        buf1, wsp, y, TTOK, DM, HID, HID, DM, nullptr, nullptr, nullptr, 0, 0);

    // routed experts (grouped, compact rows; total assignments = 2*TTOK)
    gemm_tc<<<dim3(HID / BN, NE * 32), 256, GEMM_SMEM>>>(
        x, wfc, buf1, 0, HID, DM, DM, HID, idx, cnt, off, (long long)DM * HID, 1);
    gemm_tc<<<dim3(HID / BN, NE * 32), 256, GEMM_SMEM>>>(
        x, wgt, buf2, 0, HID, DM, DM, HID, idx, cnt, off, (long long)DM * HID, 1);
    fuse_k<<<(2 * TTOK * HID / 4 + 255) / 256, 256>>>((float4*)buf1, (const float4*)buf2,
                                                      2 * TTOK * HID / 4);
    gemm_tc<<<dim3(DM / BN, NE * 32), 256, GEMM_SMEM>>>(
        buf1, wpj, rout, 0, DM, HID, HID, DM, nullptr, cnt, off, (long long)HID * DM, 1);

    combine_k<<<(YN / 4 + 255) / 256, 256>>>((float4*)y, (const float4*)rout);
    tail_k<<<1, 256>>>(y, out_size);
}

// round 17
// speedup vs baseline: 1.0538x; 1.0390x over previous
#include <cuda_runtime.h>
#include <cstdint>

#define TTOK 4096
#define DM   1024
#define HID  4096
#define NE   8
#define YN   (TTOK * DM)
#define HROWS (3 * TTOK)        // 8192 routed compact + 4096 shared

// GEMM tiling
#define BM 128
#define BN 256
#define BK 32
#define NST 3
#define A_LD 36                  // 32 + 4 pad (floats)
#define B_LD 264                 // 256 + 8 pad (floats)
#define ASZ (BM * A_LD * 4)      // 18432 B
#define BSZ (BK * B_LD * 4)      // 33792 B
#define STG (ASZ + BSZ)          // 52224 B
#define GSMEM (NST * STG)        // 156672 B

// ---- static scratch ----
__device__ float g_buf1[HROWS * HID];    // fc outputs -> fused h  (201 MB)
__device__ float g_buf2[HROWS * HID];    // gate outputs           (201 MB)
__device__ float g_rout[2 * TTOK * DM];  // routed proj outputs
__device__ float g_scores[TTOK * NE];
__device__ int   g_idx[NE * TTOK];
__device__ int   g_apos[2 * TTOK];
__device__ float g_aw[2 * TTOK];
__device__ int   g_cnt[NE];
__device__ int   g_off[NE];

// ---- helpers ----
__device__ __forceinline__ uint32_t smem_u32(const void* p) {
    uint32_t a;
    asm("{ .reg .u64 t; cvta.to.shared.u64 t, %1; cvt.u32.u64 %0, t; }" : "=r"(a) : "l"(p));
    return a;
}
__device__ __forceinline__ float to_tf32(float x) {
    unsigned u; asm("cvt.rna.tf32.f32 %0, %1;" : "=r"(u) : "f"(x));
    return __uint_as_float(u);
}
__device__ __forceinline__ void mma8(float* d, const float* a, const float* b) {
    const unsigned* A = reinterpret_cast<const unsigned*>(a);
    const unsigned* B = reinterpret_cast<const unsigned*>(b);
    asm volatile("mma.sync.aligned.m16n8k8.row.col.f32.tf32.tf32.f32 "
                 "{%0,%1,%2,%3}, {%4,%5,%6,%7}, {%8,%9}, {%0,%1,%2,%3};\n"
                 : "+f"(d[0]), "+f"(d[1]), "+f"(d[2]), "+f"(d[3])
                 : "r"(A[0]), "r"(A[1]), "r"(A[2]), "r"(A[3]), "r"(B[0]), "r"(B[1]));
}
__device__ __forceinline__ void cpasync16(uint32_t dst, const float* src) {
    asm volatile("cp.async.cg.shared.global [%0], [%1], 16;" :: "r"(dst), "l"(src));
}
#define CP_COMMIT() asm volatile("cp.async.commit_group;" ::: "memory")
#define CP_WAIT1()  asm volatile("cp.async.wait_group 1;" ::: "memory")

// ============ merged MoE GEMM ============
// blockIdx.y = mslot in [0,288): [0,256) -> routed (e = ms>>5, mt = ms&31, ragged by g_cnt);
//                                 [256,288) -> shared expert (mt = ms-256, 128 rows each).
// mode 0 (fc|gate): A rows from X (=x): routed rows gathered via g_idx, shared rows direct.
//   K=DM. blockIdx.x = jn in [0,32): jn<16 -> fc half (B=Wr0[e]/Ws0, C=C0), else gate half
//   (B=Wr1[e]/Ws1, C=C1). C row = compact h row (routed: g_off[e]+base; shared: 8192+mt*128).
// mode 1 (proj): A rows = compact h rows of X (=buf1), direct. K=HID. blockIdx.x = jn in [0,4).
//   B = Wr0[e]/Ws0; C: routed -> C0 (=g_rout, compact row), shared -> C1 (=y, row mt*128).
__global__ __launch_bounds__(256)
void gemm_k(const float* __restrict__ X,
            const float* __restrict__ Wr0, const float* __restrict__ Wr1,
            const float* __restrict__ Ws0, const float* __restrict__ Ws1,
            float* __restrict__ C0, float* __restrict__ C1, int mode)
{
    extern __shared__ float smem[];
    const int tid = threadIdx.x;
    const int jn = blockIdx.x;
    const int ms = blockIdx.y;

    int valid, e = 0, mt, base = 0;
    bool shexp;
    if (ms < 256) {
        e = ms >> 5; mt = ms & 31;
        int cnt = g_cnt[e]; base = mt * 128;
        if (base >= cnt) return;
        valid = cnt - base; if (valid > 128) valid = 128;
        shexp = false;
    } else {
        mt = ms - 256; valid = 128; shexp = true;
    }
    const int crowH = shexp ? (2 * TTOK + mt * 128) : (g_off[e] + base);  // compact h row base

    const int K   = mode ? HID : DM;
    const int lda = mode ? HID : DM;
    const int Nw  = mode ? DM : HID;     // weight row width
    const int ldc = mode ? DM : HID;

    // select B, C, column offset
    const float* Bp;
    float* Cp;
    int ccol, crowC;
    if (mode == 0) {
        int half = (jn >> 4);            // 0 = fc, 1 = gate
        int jn2 = jn & 15;
        ccol = jn2 * BN;
        if (half == 0) { Bp = shexp ? Ws0 : (Wr0 + (long long)e * DM * HID); Cp = C0; }
        else           { Bp = shexp ? Ws1 : (Wr1 + (long long)e * DM * HID); Cp = C1; }
        crowC = crowH;
    } else {
        ccol = jn * BN;
        if (shexp) { Bp = Ws0; Cp = C1; crowC = mt * 128; }
        else       { Bp = Wr0 + (long long)e * HID * DM; Cp = C0; crowC = crowH; }
    }

    // ---- fill assignments ----
    // A: thread owns row fr = tid>>1, 16-float half hq = tid&1 (4 cp16)
    const int fr = tid >> 1, hq = tid & 1;
    int arow;
    if (mode == 0) {
        if (shexp) arow = mt * 128 + fr;
        else       arow = g_idx[e * TTOK + base + (fr < valid ? fr : valid - 1)];
    } else {
        arow = crowH + fr;               // compact h rows, direct
    }
    const float* asrc = X + (long long)arow * lda + hq * 16;
    // B: thread owns k-row kr = tid>>3, col-quad qb = tid&7 (8 cp16, stride 32 floats)
    const int kr = tid >> 3, qb = tid & 7;
    const float* bsrc = Bp + (long long)kr * Nw + ccol + qb * 4;

    const uint32_t sb = smem_u32(smem);
    const int nk = K / BK;

    auto issue = [&](int s, int k0) {
        if (k0 < K) {
            uint32_t st = sb + s * STG;
            uint32_t ad = st + fr * (A_LD * 4) + hq * 64;
#pragma unroll
            for (int i = 0; i < 4; i++) cpasync16(ad + i * 16, asrc + k0 + i * 4);
            uint32_t bd = st + ASZ + kr * (B_LD * 4) + qb * 16;
            const float* bs = bsrc + (long long)k0 * Nw;
#pragma unroll
            for (int i = 0; i < 8; i++) cpasync16(bd + i * 128, bs + i * 32);
        }
        CP_COMMIT();
    };

    issue(0, 0);
    issue(1, BK);

    // ---- compute mapping: 8 warps = 2(m) x 4(n), warp tile 64x64 ----
    const int wid = tid >> 5, lane = tid & 31;
    const int wm = (wid & 1) << 6;
    const int wn = (wid >> 1) << 6;
    const int g = lane >> 2, tg = lane & 3;

    float acc[4][8][4];
#pragma unroll
    for (int i = 0; i < 4; i++)
#pragma unroll
        for (int j = 0; j < 8; j++)
#pragma unroll
            for (int c = 0; c < 4; c++) acc[i][j][c] = 0.f;

    for (int it = 0; it < nk; ++it) {
        CP_WAIT1();
        __syncthreads();
        issue((it + 2) % NST, (it + 2) * BK);

        const float* Sa = smem + (it % NST) * (STG / 4);
        const float* Sb = Sa + (ASZ / 4);
#pragma unroll
        for (int s = 0; s < 4; s++) {
            const int ks = s << 3;
            float af[4][4], bf[8][2];
#pragma unroll
            for (int j = 0; j < 8; j++) {
                int n = wn + (j << 3) + g;
                bf[j][0] = to_tf32(Sb[(ks + tg) * B_LD + n]);
                bf[j][1] = to_tf32(Sb[(ks + tg + 4) * B_LD + n]);
            }
#pragma unroll
            for (int i = 0; i < 4; i++) {
                int m = wm + (i << 4) + g;
                af[i][0] = to_tf32(Sa[m * A_LD + ks + tg]);
                af[i][1] = to_tf32(Sa[(m + 8) * A_LD + ks + tg]);
                af[i][2] = to_tf32(Sa[m * A_LD + ks + tg + 4]);
                af[i][3] = to_tf32(Sa[(m + 8) * A_LD + ks + tg + 4]);
            }
#pragma unroll
            for (int i = 0; i < 4; i++)
#pragma unroll
                for (int j = 0; j < 8; j++) mma8(acc[i][j], af[i], bf[j]);
        }
    }

    // ---- epilogue ----
#pragma unroll
    for (int i = 0; i < 4; i++) {
        int m0 = wm + (i << 4) + g, m1 = m0 + 8;
#pragma unroll
        for (int j = 0; j < 8; j++) {
            int c = ccol + wn + (j << 3) + (tg << 1);
            if (m0 < valid)
                *(float2*)&Cp[(long long)(crowC + m0) * ldc + c] = make_float2(acc[i][j][0], acc[i][j][1]);
            if (m1 < valid)
                *(float2*)&Cp[(long long)(crowC + m1) * ldc + c] = make_float2(acc[i][j][2], acc[i][j][3]);
        }
    }
}

// ============ router & small kernels ============
__global__ void zero_k() {
    if (threadIdx.x < NE) g_cnt[threadIdx.x] = 0;
}

__global__ void router_k(const float* __restrict__ x, const float* __restrict__ wr) {
    int t = blockIdx.x;
    const float* xr = x + (long long)t * DM;
    double acc[NE];
#pragma unroll
    for (int e = 0; e < NE; e++) acc[e] = 0.0;
    for (int d = threadIdx.x; d < DM; d += 256) {
        double xv = (double)xr[d];
#pragma unroll
        for (int e = 0; e < NE; e++) acc[e] += xv * (double)wr[e * DM + d];
    }
#pragma unroll
    for (int e = 0; e < NE; e++)
        for (int o = 16; o > 0; o >>= 1) acc[e] += __shfl_down_sync(0xffffffffu, acc[e], o);
    __shared__ double sred[NE][8];
    int lane = threadIdx.x & 31, w = threadIdx.x >> 5;
    if (lane == 0) {
#pragma unroll
        for (int e = 0; e < NE; e++) sred[e][w] = acc[e];
    }
    __syncthreads();
    if (threadIdx.x != 0) return;

    float lg[NE];
#pragma unroll
    for (int e = 0; e < NE; e++) {
        double s = 0.0;
#pragma unroll
        for (int k = 0; k < 8; k++) s += sred[e][k];
        lg[e] = (float)s;
    }
    float m = lg[0];
#pragma unroll
    for (int e = 1; e < NE; e++) m = fmaxf(m, lg[e]);
    float ex[NE], ssum = 0.f;
#pragma unroll
    for (int e = 0; e < NE; e++) { ex[e] = expf(lg[e] - m); ssum += ex[e]; }
    float sc[NE];
#pragma unroll
    for (int e = 0; e < NE; e++) { sc[e] = ex[e] / ssum; g_scores[t * NE + e] = sc[e]; }

    float gs[4];
#pragma unroll
    for (int gi = 0; gi < 4; gi++) gs[gi] = fmaxf(sc[2 * gi], sc[2 * gi + 1]);
    int g1 = 0;
#pragma unroll
    for (int gi = 1; gi < 4; gi++) if (gs[gi] > gs[g1]) g1 = gi;
    int g2 = -1; float bv = -1.f;
#pragma unroll
    for (int gi = 0; gi < 4; gi++) if (gi != g1 && gs[gi] > bv) { bv = gs[gi]; g2 = gi; }

    float msc[NE];
#pragma unroll
    for (int e = 0; e < NE; e++)
        msc[e] = (((e >> 1) == g1) || ((e >> 1) == g2)) ? sc[e] : -1.f;
    int i1 = 0;
#pragma unroll
    for (int e = 1; e < NE; e++) if (msc[e] > msc[i1]) i1 = e;
    int i2 = -1; float b2 = -2.f;
#pragma unroll
    for (int e = 0; e < NE; e++) if (e != i1 && msc[e] > b2) { b2 = msc[e]; i2 = e; }

    int s1 = atomicAdd(&g_cnt[i1], 1);
    g_idx[i1 * TTOK + s1] = t;
    g_apos[2 * t] = i1 * TTOK + s1;
    g_aw[2 * t] = sc[i1];
    int s2 = atomicAdd(&g_cnt[i2], 1);
    g_idx[i2 * TTOK + s2] = t;
    g_apos[2 * t + 1] = i2 * TTOK + s2;
    g_aw[2 * t + 1] = sc[i2];
}

__global__ void offsets_k() {
    if (threadIdx.x == 0) {
        int s = 0;
#pragma unroll
        for (int e = 0; e < NE; e++) { g_off[e] = s; s += g_cnt[e]; }
    }
}
__global__ void translate_k() {
    int t = blockIdx.x * blockDim.x + threadIdx.x;
    if (t >= 2 * TTOK) return;
    int code = g_apos[t];
    g_apos[t] = g_off[code >> 12] + (code & (TTOK - 1));
}

__global__ void fuse_k(float4* __restrict__ h, const float4* __restrict__ gt, int n4) {
    int i = blockIdx.x * blockDim.x + threadIdx.x;
    if (i >= n4) return;
    float4 a = h[i], b = gt[i];
    a.x *= b.x / (1.f + __expf(-b.x));
    a.y *= b.y / (1.f + __expf(-b.y));
    a.z *= b.z / (1.f + __expf(-b.z));
    a.w *= b.w / (1.f + __expf(-b.w));
    h[i] = a;
}

__global__ void combine_k(float4* __restrict__ y, const float4* __restrict__ rout) {
    int v = blockIdx.x * blockDim.x + threadIdx.x;
    if (v >= YN / 4) return;
    int t = v >> 8, n = v & 255;
    int p0 = g_apos[2 * t], p1 = g_apos[2 * t + 1];
    float w0 = g_aw[2 * t], w1 = g_aw[2 * t + 1];
    float4 a = y[v];
    float4 q0 = rout[p0 * 256 + n], q1 = rout[p1 * 256 + n];
    a.x += w0 * q0.x + w1 * q1.x;
    a.y += w0 * q0.y + w1 * q1.y;
    a.z += w0 * q0.z + w1 * q1.z;
    a.w += w0 * q0.w + w1 * q1.w;
    y[v] = a;
}

__global__ void tail_k(float* out, int out_size) {
    __shared__ float sh[NE][256];
    int tid = threadIdx.x;
    float ps[NE];
#pragma unroll
    for (int e = 0; e < NE; e++) ps[e] = 0.f;
    for (int t = tid; t < TTOK; t += 256)
#pragma unroll
        for (int e = 0; e < NE; e++) ps[e] += g_scores[t * NE + e];
#pragma unroll
    for (int e = 0; e < NE; e++) sh[e][tid] = ps[e];
    __syncthreads();
    __shared__ float pe[NE];
    if (tid < NE) {
        float s = 0.f;
        for (int k = 0; k < 256; k++) s += sh[tid][k];
        pe[tid] = s / (float)TTOK;
    }
    __syncthreads();
    if (tid == 0 && out_size > YN) {
        float lb = 0.f;
#pragma unroll
        for (int e = 0; e < NE; e++)
            lb += ((float)g_cnt[e] / (float)(TTOK * 2)) * pe[e];
        out[YN] = (float)NE * lb - 1.f;
    }
    if (tid < NE && out_size >= YN + 1 + NE)
        out[YN + 1 + tid] = (float)g_cnt[tid];
}

// ============ launch ============
extern "C" void kernel_launch(void* const* d_in, const int* in_sizes, int n_in,
                              void* d_out, int out_size) {
    const float* x   = (const float*)d_in[0];
    const float* wr  = (const float*)d_in[1];
    const float* wfc = (const float*)d_in[2];
    const float* wgt = (const float*)d_in[3];
    const float* wpj = (const float*)d_in[4];
    const float* wsf = (const float*)d_in[5];
    const float* wsg = (const float*)d_in[6];
    const float* wsp = (const float*)d_in[7];
    float* y = (float*)d_out;

    cudaFuncSetAttribute(gemm_k, cudaFuncAttributeMaxDynamicSharedMemorySize, GSMEM);

    void *p1, *p2, *pr;
    cudaGetSymbolAddress(&p1, g_buf1);
    cudaGetSymbolAddress(&p2, g_buf2);
    cudaGetSymbolAddress(&pr, g_rout);
    float* buf1 = (float*)p1;
    float* buf2 = (float*)p2;
    float* rout = (float*)pr;

    zero_k<<<1, 32>>>();
    router_k<<<TTOK, 256>>>(x, wr);
    offsets_k<<<1, 32>>>();
    translate_k<<<(2 * TTOK + 255) / 256, 256>>>();

    // fc|gate for routed + shared experts, one launch:
    // grid.x: 32 n-tiles (16 fc over HID + 16 gate over HID); grid.y: 288 m-slots
    gemm_k<<<dim3(32, 288), 256, GSMEM>>>(x, wfc, wgt, wsf, wsg, buf1, buf2, 0);

    // fused SwiGLU over all compact h rows (routed 8192 + shared 4096)
    fuse_k<<<(HROWS * HID / 4 + 255) / 256, 256>>>((float4*)buf1, (const float4*)buf2,
                                                   HROWS * HID / 4);

    // proj for routed (-> g_rout) + shared (-> y), one launch
    gemm_k<<<dim3(4, 288), 256, GSMEM>>>(buf1, wpj, nullptr, wsp, nullptr, rout, y, 1);

    combine_k<<<(YN / 4 + 255) / 256, 256>>>((float4*)y, (const float4*)rout);
    tail_k<<<1, 256>>>(y, out_size);
}